// round 4
// baseline (speedup 1.0000x reference)
#include <cuda_runtime.h>
#include <math.h>

#define BB 32
#define TT 2048
#define HH 512
#define UU 32
#define ROWS (BB*TT)   // 65536

typedef unsigned long long u64t;

__device__ float g_delta[(size_t)ROWS * UU];   // 8 MB
__device__ float g_sum[BB * HH];
__device__ float g_inv[BB * HH];

__device__ __forceinline__ u64t pack2(float lo, float hi) {
    u64t r; asm("mov.b64 %0, {%1, %2};" : "=l"(r) : "f"(lo), "f"(hi)); return r;
}
__device__ __forceinline__ float2 unpack2(u64t v) {
    float2 f; asm("mov.b64 {%0, %1}, %2;" : "=f"(f.x), "=f"(f.y) : "l"(v)); return f;
}
__device__ __forceinline__ u64t dup2(float v) {
    u64t r; asm("mov.b64 %0, {%1, %1};" : "=l"(r) : "f"(v)); return r;
}
__device__ __forceinline__ void ffma2(u64t& d, u64t a, u64t b) {
    asm("fma.rn.f32x2 %0, %1, %2, %3;" : "=l"(d) : "l"(a), "l"(b), "l"(d));
}

// =====================================================================
__global__ void k_zero() {
    int i = blockIdx.x * 256 + threadIdx.x;
    if (i < BB * HH) g_sum[i] = 0.0f;
}

// =====================================================================
// K1: delta = lambd*tanh(x@Wx+bx) + (1-lambd)*tanh(t@Wt+bt)
// 256 threads, 256 rows/block. Thread tile: 4 rows x 8 u, f32x2 = (x-path, t-path).
// kc=32 chunks (full 128B lines, read once). A double-buffered, W chunk-staged.
// sA layout: [k][rg(64), stride 48B][4 rows x 8B]  (conflict-free)
// sW layout: [k][ug(4), stride 80B][8 u x 8B]      (conflict-free)
// =====================================================================
#define K1_KSTR 3072              // 64*48
#define K1_ABUF (32*K1_KSTR)      // 98304
#define K1_WKSTR 320              // 4*80
#define K1_WBUF (32*K1_WKSTR)     // 10240
#define K1_SMEM (2*K1_ABUF + 2*K1_WBUF)  // 217088

__global__ void __launch_bounds__(256, 1)
k_delta(const float* __restrict__ x, const float* __restrict__ t,
        const float* __restrict__ kx, const float* __restrict__ kt,
        const float* __restrict__ bx, const float* __restrict__ bt,
        const float* __restrict__ lambd)
{
    extern __shared__ char smem[];
    char* sA = smem;
    char* sW = smem + 2 * K1_ABUF;

    const int tid = threadIdx.x;
    const int rg = tid >> 2;           // 0..63 (4 rows each)
    const int ug = tid & 3;            // 0..3  (8 u each)
    const int rowBase = blockIdx.x * 256;

    // acc[r][j] = (gamma_partial, beta_partial), init with biases
    u64t acc[4][8];
#pragma unroll
    for (int j = 0; j < 8; j++) {
        const u64t b0 = pack2(bx[ug * 8 + j], bt[ug * 8 + j]);
#pragma unroll
        for (int r = 0; r < 4; r++) acc[r][j] = b0;
    }

    // staging roles
    const int srg = tid >> 2, srr = tid & 3;                 // A: row = tid
    const float* xr0 = x + (size_t)(rowBase + tid) * HH;
    const float* tr0 = t + (size_t)(rowBase + tid) * HH;
    const int kk = tid >> 3;                                  // W: k row
    const int u4 = (tid & 7) * 4;                             // 4 consecutive u
    const int wbase = kk * K1_WKSTR + (u4 >> 3) * 80 + (u4 & 7) * 8;

    // ---- stage one chunk into buffer bsel ----
    auto stage = [&](int c, int bsel) {
        char* ad = sA + bsel * K1_ABUF;
        const float4* xq = (const float4*)(xr0 + c * 32);
        const float4* tq = (const float4*)(tr0 + c * 32);
        const int abase = srg * 48 + srr * 8;
#pragma unroll
        for (int q = 0; q < 8; q++) {
            const float4 xv = xq[q], tv = tq[q];
            char* p = ad + (q * 4) * K1_KSTR + abase;
            *(u64t*)(p)               = pack2(xv.x, tv.x);
            *(u64t*)(p + K1_KSTR)     = pack2(xv.y, tv.y);
            *(u64t*)(p + 2 * K1_KSTR) = pack2(xv.z, tv.z);
            *(u64t*)(p + 3 * K1_KSTR) = pack2(xv.w, tv.w);
        }
        char* wd = sW + bsel * K1_WBUF;
        const float4 wxv = *(const float4*)(kx + (size_t)(c * 32 + kk) * UU + u4);
        const float4 wtv = *(const float4*)(kt + (size_t)(c * 32 + kk) * UU + u4);
        *(u64t*)(wd + wbase)      = pack2(wxv.x, wtv.x);
        *(u64t*)(wd + wbase + 8)  = pack2(wxv.y, wtv.y);
        *(u64t*)(wd + wbase + 16) = pack2(wxv.z, wtv.z);
        *(u64t*)(wd + wbase + 24) = pack2(wxv.w, wtv.w);
    };

    stage(0, 0);
    __syncthreads();

    for (int c = 0; c < 16; c++) {
        if (c < 15) stage(c + 1, (c + 1) & 1);

        const char* A = sA + (c & 1) * K1_ABUF + rg * 48;
        const char* W = sW + (c & 1) * K1_WBUF + ug * 80;
#pragma unroll 4
        for (int k = 0; k < 32; k++) {
            const ulonglong2 a01 = *(const ulonglong2*)(A + k * K1_KSTR);
            const ulonglong2 a23 = *(const ulonglong2*)(A + k * K1_KSTR + 16);
            const ulonglong2 w01 = *(const ulonglong2*)(W + k * K1_WKSTR);
            const ulonglong2 w23 = *(const ulonglong2*)(W + k * K1_WKSTR + 16);
            const ulonglong2 w45 = *(const ulonglong2*)(W + k * K1_WKSTR + 32);
            const ulonglong2 w67 = *(const ulonglong2*)(W + k * K1_WKSTR + 48);
            u64t a[4] = {a01.x, a01.y, a23.x, a23.y};
            u64t w[8] = {w01.x, w01.y, w23.x, w23.y, w45.x, w45.y, w67.x, w67.y};
#pragma unroll
            for (int r = 0; r < 4; r++)
#pragma unroll
                for (int j = 0; j < 8; j++)
                    ffma2(acc[r][j], a[r], w[j]);
        }
        __syncthreads();
    }

    // epilogue: tanh + lambda-combine, store delta
#pragma unroll
    for (int r = 0; r < 4; r++) {
        const int row = rowBase + rg * 4 + r;
        const float lam = __ldg(lambd + (row & (TT - 1)));
        float* drow = g_delta + (size_t)row * UU + ug * 8;
#pragma unroll
        for (int j = 0; j < 8; j += 2) {
            const float2 v0 = unpack2(acc[r][j]);
            const float2 v1 = unpack2(acc[r][j + 1]);
            float2 o;
            o.x = lam * tanhf(v0.x) + (1.0f - lam) * tanhf(v0.y);
            o.y = lam * tanhf(v1.x) + (1.0f - lam) * tanhf(v1.y);
            *(float2*)(drow + j) = o;
        }
    }
}

// =====================================================================
// K2: e = exp(delta @ Wa) -> d_out, plus per-(b,h) sums of e.
// 256 threads = 8 warps; warp = 8 rows x 512 h; thread = 8 rows x 16 h.
// delta broadcast from registers via shfl; Wa from smem (strided, conflict-free).
// Max-subtraction skipped: |score| <= ~3.4.
// =====================================================================
#define K2_SMEM (UU*256*8 + HH*4)   // 67584

__global__ void __launch_bounds__(256, 1)
k_scores(const float* __restrict__ ka, float* __restrict__ out) {
    extern __shared__ char smem[];
    u64t* sWa = (u64t*)smem;                       // [u][hp 256] (h even, h odd)
    float* ssum = (float*)(smem + UU * 256 * 8);

    const int tid = threadIdx.x;
    const int lane = tid & 31;
    const int w = tid >> 5;

    for (int i = tid; i < UU * 256; i += 256) {
        const int u = i >> 8, hp = i & 255;
        const float2 wv = *(const float2*)(ka + (size_t)u * HH + 2 * hp);
        sWa[i] = pack2(wv.x, wv.y);
    }
    for (int i = tid; i < HH; i += 256) ssum[i] = 0.0f;
    __syncthreads();

    const int row0 = blockIdx.x * 64 + w * 8;

    float d[8];
#pragma unroll
    for (int r = 0; r < 8; r++)
        d[r] = g_delta[(size_t)(row0 + r) * UU + lane];

    u64t acc[8][8];
#pragma unroll
    for (int r = 0; r < 8; r++)
#pragma unroll
        for (int j = 0; j < 8; j++) acc[r][j] = 0ull;

#pragma unroll 4
    for (int u = 0; u < UU; u++) {
        u64t dd[8];
#pragma unroll
        for (int r = 0; r < 8; r++)
            dd[r] = dup2(__shfl_sync(0xffffffffu, d[r], u));
        const u64t* wrow = sWa + u * 256 + lane;
        u64t wv[8];
#pragma unroll
        for (int j = 0; j < 8; j++) wv[j] = wrow[j * 32];
#pragma unroll
        for (int r = 0; r < 8; r++)
#pragma unroll
            for (int j = 0; j < 8; j++)
                ffma2(acc[r][j], dd[r], wv[j]);
    }

    float sx[8], sy[8];
#pragma unroll
    for (int j = 0; j < 8; j++) { sx[j] = 0.0f; sy[j] = 0.0f; }

#pragma unroll
    for (int r = 0; r < 8; r++) {
        float* orow = out + (size_t)(row0 + r) * HH;
#pragma unroll
        for (int j = 0; j < 8; j++) {
            const float2 v = unpack2(acc[r][j]);
            const float e0 = __expf(v.x);
            const float e1 = __expf(v.y);
            *(float2*)(orow + 2 * (lane + 32 * j)) = make_float2(e0, e1);
            sx[j] += e0; sy[j] += e1;
        }
    }

#pragma unroll
    for (int j = 0; j < 8; j++) {
        atomicAdd(&ssum[2 * (lane + 32 * j)], sx[j]);
        atomicAdd(&ssum[2 * (lane + 32 * j) + 1], sy[j]);
    }
    __syncthreads();

    const int b = blockIdx.x >> 5;   // 32 blocks (64 rows each) per batch
    for (int i = tid; i < HH; i += 256)
        atomicAdd(&g_sum[b * HH + i], ssum[i]);
}

// =====================================================================
__global__ void k_inv() {
    int i = blockIdx.x * 256 + threadIdx.x;
    if (i < BB * HH) g_inv[i] = 1.0f / g_sum[i];
}

__global__ void __launch_bounds__(256)
k_norm(float* __restrict__ out) {
    const size_t i4 = (size_t)blockIdx.x * 256 + threadIdx.x;
    float4 e = ((float4*)out)[i4];
    const size_t i = i4 * 4;
    const int h = (int)(i & (size_t)(HH - 1));
    const int b = (int)(i >> 20);    // T*H = 2^20
    const float4 inv = *(const float4*)(g_inv + b * HH + h);
    e.x *= inv.x; e.y *= inv.y; e.z *= inv.z; e.w *= inv.w;
    ((float4*)out)[i4] = e;
}

// =====================================================================
extern "C" void kernel_launch(void* const* d_in, const int* in_sizes, int n_in,
                              void* d_out, int out_size) {
    const float* x     = (const float*)d_in[0];
    const float* t     = (const float*)d_in[1];
    const float* kx    = (const float*)d_in[2];
    const float* kt    = (const float*)d_in[3];
    const float* ka    = (const float*)d_in[4];
    const float* bx    = (const float*)d_in[5];
    const float* bt    = (const float*)d_in[6];
    const float* lambd = (const float*)d_in[7];
    float* out = (float*)d_out;

    cudaFuncSetAttribute(k_delta, cudaFuncAttributeMaxDynamicSharedMemorySize, K1_SMEM);
    cudaFuncSetAttribute(k_scores, cudaFuncAttributeMaxDynamicSharedMemorySize, K2_SMEM);

    k_zero<<<64, 256>>>();
    k_delta<<<ROWS / 256, 256, K1_SMEM>>>(x, t, kx, kt, bx, bt, lambd);
    k_scores<<<ROWS / 64, 256, K2_SMEM>>>(ka, out);
    k_inv<<<64, 256>>>();
    k_norm<<<(ROWS * HH) / 4 / 256, 256>>>(out);
}

// round 6
// speedup vs baseline: 1.3627x; 1.3627x over previous
#include <cuda_runtime.h>
#include <math.h>

#define BB 32
#define TT 2048
#define HH 512
#define UU 32
#define ROWS (BB*TT)   // 65536

typedef unsigned long long u64t;

__device__ float g_delta[(size_t)ROWS * UU];   // 8 MB
__device__ float g_sum[BB * HH];

__device__ __forceinline__ u64t pack2(float lo, float hi) {
    u64t r; asm("mov.b64 %0, {%1, %2};" : "=l"(r) : "f"(lo), "f"(hi)); return r;
}
__device__ __forceinline__ float2 unpack2(u64t v) {
    float2 f; asm("mov.b64 {%0, %1}, %2;" : "=f"(f.x), "=f"(f.y) : "l"(v)); return f;
}
__device__ __forceinline__ u64t dup2(float v) {
    u64t r; asm("mov.b64 %0, {%1, %1};" : "=l"(r) : "f"(v)); return r;
}
__device__ __forceinline__ void ffma2(u64t& d, u64t a, u64t b) {
    asm("fma.rn.f32x2 %0, %1, %2, %3;" : "=l"(d) : "l"(a), "l"(b), "l"(d));
}
__device__ __forceinline__ float fast_tanh(float a) {
    // tanh(a) = 1 - 2/(exp(2a)+1); |score| small so __expf is safe/accurate
    return 1.0f - 2.0f / (__expf(2.0f * a) + 1.0f);
}

// =====================================================================
// K1: delta = lambd*tanh(x@Wx+bx) + (1-lambd)*tanh(t@Wt+bt)
// 256 threads, 256 rows/block, 16 chunks of kc=32.
// Thread tile 4 rows x 8 u; f32x2 = (x-path, t-path).
// sA: [k][row] pairs, k-stride 2320B, row offset row*8+(row>>4)*16
//     -> compute LDS.128 conflict-free; staged coalesced (4 rows/LDG.128).
// sW: [k][ug(4) x 80B], conflict-free on compute.
// Also zeroes g_sum (blocks 0..63) for the downstream kernel.
// =====================================================================
#define K1_KSTR 2320
#define K1_ABUF (32*K1_KSTR)      // 74240
#define K1_WKSTR 320
#define K1_WBUF (32*K1_WKSTR)     // 10240
#define K1_SMEM (2*K1_ABUF + 2*K1_WBUF)  // 168960

__device__ __forceinline__ int aoff(int row) { return row * 8 + (row >> 4) * 16; }

__global__ void __launch_bounds__(256, 1)
k_delta(const float* __restrict__ x, const float* __restrict__ t,
        const float* __restrict__ kx, const float* __restrict__ kt,
        const float* __restrict__ bx, const float* __restrict__ bt,
        const float* __restrict__ lambd)
{
    extern __shared__ char smem[];
    char* sA = smem;
    char* sW = smem + 2 * K1_ABUF;

    const int tid = threadIdx.x;
    const int lane = tid & 31;
    const int w = tid >> 5;
    const int rg = tid >> 2;           // 0..63, 4 rows each
    const int ug = tid & 3;            // 0..3, 8 u each
    const int rowBase = blockIdx.x * 256;

    if (blockIdx.x < 64) g_sum[blockIdx.x * 256 + tid] = 0.0f;  // zero for k_scores

    u64t acc[4][8];
#pragma unroll
    for (int j = 0; j < 8; j++) {
        const u64t b0 = pack2(bx[ug * 8 + j], bt[ug * 8 + j]);
#pragma unroll
        for (int r = 0; r < 4; r++) acc[r][j] = b0;
    }

    // staging roles
    const int srow = w * 32 + (lane >> 3);    // + p*4 per pass
    const int sk4 = (lane & 7) * 4;           // 4 consecutive k
    const int wk = tid >> 3;                  // W: k row 0..31
    const int wu4 = (tid & 7) * 4;            // 4 consecutive u
    const int wbase = wk * K1_WKSTR + (wu4 >> 3) * 80 + (wu4 & 7) * 8;

    auto stage = [&](int c, int bsel) {
        char* ad = sA + bsel * K1_ABUF;
#pragma unroll
        for (int p = 0; p < 8; p++) {
            const int row = srow + p * 4;
            const size_t goff = (size_t)(rowBase + row) * HH + c * 32 + sk4;
            const float4 xv = *(const float4*)(x + goff);
            const float4 tv = *(const float4*)(t + goff);
            char* dst = ad + sk4 * K1_KSTR + aoff(row);
            *(u64t*)(dst)               = pack2(xv.x, tv.x);
            *(u64t*)(dst + K1_KSTR)     = pack2(xv.y, tv.y);
            *(u64t*)(dst + 2*K1_KSTR)   = pack2(xv.z, tv.z);
            *(u64t*)(dst + 3*K1_KSTR)   = pack2(xv.w, tv.w);
        }
        char* wd = sW + bsel * K1_WBUF;
        const float4 wxv = *(const float4*)(kx + (size_t)(c * 32 + wk) * UU + wu4);
        const float4 wtv = *(const float4*)(kt + (size_t)(c * 32 + wk) * UU + wu4);
        *(u64t*)(wd + wbase)      = pack2(wxv.x, wtv.x);
        *(u64t*)(wd + wbase + 8)  = pack2(wxv.y, wtv.y);
        *(u64t*)(wd + wbase + 16) = pack2(wxv.z, wtv.z);
        *(u64t*)(wd + wbase + 24) = pack2(wxv.w, wtv.w);
    };

    stage(0, 0);
    __syncthreads();

    const int abase = aoff(rg * 4);

    for (int c = 0; c < 16; c++) {
        if (c < 15) stage(c + 1, (c + 1) & 1);

        const char* A = sA + (c & 1) * K1_ABUF + abase;
        const char* W = sW + (c & 1) * K1_WBUF + ug * 80;
#pragma unroll 4
        for (int k = 0; k < 32; k++) {
            const ulonglong2 a01 = *(const ulonglong2*)(A + k * K1_KSTR);
            const ulonglong2 a23 = *(const ulonglong2*)(A + k * K1_KSTR + 16);
            const ulonglong2 w01 = *(const ulonglong2*)(W + k * K1_WKSTR);
            const ulonglong2 w23 = *(const ulonglong2*)(W + k * K1_WKSTR + 16);
            const ulonglong2 w45 = *(const ulonglong2*)(W + k * K1_WKSTR + 32);
            const ulonglong2 w67 = *(const ulonglong2*)(W + k * K1_WKSTR + 48);
            u64t a[4] = {a01.x, a01.y, a23.x, a23.y};
            u64t wv[8] = {w01.x, w01.y, w23.x, w23.y, w45.x, w45.y, w67.x, w67.y};
#pragma unroll
            for (int r = 0; r < 4; r++)
#pragma unroll
                for (int j = 0; j < 8; j++)
                    ffma2(acc[r][j], a[r], wv[j]);
        }
        __syncthreads();
    }

#pragma unroll
    for (int r = 0; r < 4; r++) {
        const int row = rowBase + rg * 4 + r;
        const float lam = __ldg(lambd + (row & (TT - 1)));
        float* drow = g_delta + (size_t)row * UU + ug * 8;
#pragma unroll
        for (int j = 0; j < 8; j += 2) {
            const float2 v0 = unpack2(acc[r][j]);
            const float2 v1 = unpack2(acc[r][j + 1]);
            float2 o;
            o.x = lam * fast_tanh(v0.x) + (1.0f - lam) * fast_tanh(v0.y);
            o.y = lam * fast_tanh(v1.x) + (1.0f - lam) * fast_tanh(v1.y);
            *(float2*)(drow + j) = o;
        }
    }
}

// =====================================================================
// K2: e = exp(delta @ Wa) -> d_out, plus per-(b,h) sums of e.
// 8 warps; warp = 8 rows x 512 h; thread = 8 rows x 16 h.
// Max-subtraction skipped: |score| <= ~3.4.
// =====================================================================
#define K2_SMEM (UU*256*8 + HH*4)   // 67584

__global__ void __launch_bounds__(256, 1)
k_scores(const float* __restrict__ ka, float* __restrict__ out) {
    extern __shared__ char smem[];
    u64t* sWa = (u64t*)smem;                       // [u][hp 256] (h even, h odd)
    float* ssum = (float*)(smem + UU * 256 * 8);

    const int tid = threadIdx.x;
    const int lane = tid & 31;
    const int w = tid >> 5;

    for (int i = tid; i < UU * 256; i += 256) {
        const int u = i >> 8, hp = i & 255;
        const float2 wv = *(const float2*)(ka + (size_t)u * HH + 2 * hp);
        sWa[i] = pack2(wv.x, wv.y);
    }
    for (int i = tid; i < HH; i += 256) ssum[i] = 0.0f;
    __syncthreads();

    const int row0 = blockIdx.x * 64 + w * 8;

    float d[8];
#pragma unroll
    for (int r = 0; r < 8; r++)
        d[r] = g_delta[(size_t)(row0 + r) * UU + lane];

    u64t acc[8][8];
#pragma unroll
    for (int r = 0; r < 8; r++)
#pragma unroll
        for (int j = 0; j < 8; j++) acc[r][j] = 0ull;

#pragma unroll 4
    for (int u = 0; u < UU; u++) {
        u64t dd[8];
#pragma unroll
        for (int r = 0; r < 8; r++)
            dd[r] = dup2(__shfl_sync(0xffffffffu, d[r], u));
        const u64t* wrow = sWa + u * 256 + lane;
        u64t wv[8];
#pragma unroll
        for (int j = 0; j < 8; j++) wv[j] = wrow[j * 32];
#pragma unroll
        for (int r = 0; r < 8; r++)
#pragma unroll
            for (int j = 0; j < 8; j++)
                ffma2(acc[r][j], dd[r], wv[j]);
    }

    float sx[8], sy[8];
#pragma unroll
    for (int j = 0; j < 8; j++) { sx[j] = 0.0f; sy[j] = 0.0f; }

#pragma unroll
    for (int r = 0; r < 8; r++) {
        float* orow = out + (size_t)(row0 + r) * HH;
#pragma unroll
        for (int j = 0; j < 8; j++) {
            const float2 v = unpack2(acc[r][j]);
            const float e0 = __expf(v.x);
            const float e1 = __expf(v.y);
            *(float2*)(orow + 2 * (lane + 32 * j)) = make_float2(e0, e1);
            sx[j] += e0; sy[j] += e1;
        }
    }

#pragma unroll
    for (int j = 0; j < 8; j++) {
        atomicAdd(&ssum[2 * (lane + 32 * j)], sx[j]);
        atomicAdd(&ssum[2 * (lane + 32 * j) + 1], sy[j]);
    }
    __syncthreads();

    const int b = blockIdx.x >> 5;   // 32 blocks (64 rows each) per batch
    for (int i = tid; i < HH; i += 256)
        atomicAdd(&g_sum[b * HH + i], ssum[i]);
}

// =====================================================================
// K3: alpha = e / sum. Block = 8 rows (4096 floats) of one batch b.
// Per-block reciprocal of that b's 512 sums in smem (no k_inv kernel).
// =====================================================================
__global__ void __launch_bounds__(256)
k_norm(float* __restrict__ out) {
    __shared__ float sinv[HH];
    const int tid = threadIdx.x;
    const int b = blockIdx.x >> 8;           // 256 blocks per batch
    sinv[tid]       = 1.0f / g_sum[b * HH + tid];
    sinv[tid + 256] = 1.0f / g_sum[b * HH + tid + 256];
    __syncthreads();

    float4* o4 = (float4*)out + (size_t)blockIdx.x * 1024;
#pragma unroll
    for (int j = 0; j < 4; j++) {
        const int i4 = j * 256 + tid;
        float4 e = o4[i4];
        const float4 inv = *(const float4*)(sinv + ((i4 * 4) & (HH - 1)));
        e.x *= inv.x; e.y *= inv.y; e.z *= inv.z; e.w *= inv.w;
        o4[i4] = e;
    }
}

// =====================================================================
extern "C" void kernel_launch(void* const* d_in, const int* in_sizes, int n_in,
                              void* d_out, int out_size) {
    const float* x     = (const float*)d_in[0];
    const float* t     = (const float*)d_in[1];
    const float* kx    = (const float*)d_in[2];
    const float* kt    = (const float*)d_in[3];
    const float* ka    = (const float*)d_in[4];
    const float* bx    = (const float*)d_in[5];
    const float* bt    = (const float*)d_in[6];
    const float* lambd = (const float*)d_in[7];
    float* out = (float*)d_out;

    cudaFuncSetAttribute(k_delta, cudaFuncAttributeMaxDynamicSharedMemorySize, K1_SMEM);
    cudaFuncSetAttribute(k_scores, cudaFuncAttributeMaxDynamicSharedMemorySize, K2_SMEM);

    k_delta<<<ROWS / 256, 256, K1_SMEM>>>(x, t, kx, kt, bx, bt, lambd);
    k_scores<<<ROWS / 64, 256, K2_SMEM>>>(ka, out);
    k_norm<<<ROWS / 8, 256>>>(out);
}

// round 9
// speedup vs baseline: 2.0484x; 1.5032x over previous
#include <cuda_runtime.h>
#include <cuda_bf16.h>
#include <math.h>
#include <stdint.h>

#define BB 32
#define TT 2048
#define HH 512
#define UU 32
#define ROWS (BB*TT)   // 65536

typedef unsigned long long u64t;
typedef unsigned int u32;

__device__ float g_delta[(size_t)ROWS * UU];          // 8 MB
__device__ float g_sum[BB * HH];
// pre-split transposed weights: [tensor][u][k] bf16; tensors: 0=Wxh 1=Wxl 2=Wth 3=Wtl
__device__ __align__(16) __nv_bfloat16 g_wb[4][UU * HH];   // 128 KB

// ---------------- helpers ----------------
__device__ __forceinline__ u64t pack2(float lo, float hi) {
    u64t r; asm("mov.b64 %0, {%1, %2};" : "=l"(r) : "f"(lo), "f"(hi)); return r;
}
__device__ __forceinline__ float2 unpack2(u64t v) {
    float2 f; asm("mov.b64 {%0, %1}, %2;" : "=f"(f.x), "=f"(f.y) : "l"(v)); return f;
}
__device__ __forceinline__ u64t dup2(float v) {
    u64t r; asm("mov.b64 %0, {%1, %1};" : "=l"(r) : "f"(v)); return r;
}
__device__ __forceinline__ void ffma2(u64t& d, u64t a, u64t b) {
    asm("fma.rn.f32x2 %0, %1, %2, %3;" : "=l"(d) : "l"(a), "l"(b), "l"(d));
}
__device__ __forceinline__ float fast_tanh(float a) {
    return 1.0f - 2.0f / (__expf(2.0f * a) + 1.0f);
}
__device__ __forceinline__ u32 b2u(__nv_bfloat162 h) { return *reinterpret_cast<u32*>(&h); }

// split 8 floats into bf16-hi (16B) and bf16-lo residual (16B)
__device__ __forceinline__ void split8(float4 a, float4 b, uint4& hi, uint4& lo) {
    __nv_bfloat162 h0 = __float22bfloat162_rn(make_float2(a.x, a.y));
    __nv_bfloat162 h1 = __float22bfloat162_rn(make_float2(a.z, a.w));
    __nv_bfloat162 h2 = __float22bfloat162_rn(make_float2(b.x, b.y));
    __nv_bfloat162 h3 = __float22bfloat162_rn(make_float2(b.z, b.w));
    float2 f0 = __bfloat1622float2(h0), f1 = __bfloat1622float2(h1);
    float2 f2 = __bfloat1622float2(h2), f3 = __bfloat1622float2(h3);
    hi = make_uint4(b2u(h0), b2u(h1), b2u(h2), b2u(h3));
    lo = make_uint4(
        b2u(__float22bfloat162_rn(make_float2(a.x - f0.x, a.y - f0.y))),
        b2u(__float22bfloat162_rn(make_float2(a.z - f1.x, a.w - f1.y))),
        b2u(__float22bfloat162_rn(make_float2(b.x - f2.x, b.y - f2.y))),
        b2u(__float22bfloat162_rn(make_float2(b.z - f3.x, b.w - f3.y))));
}

__device__ __forceinline__ void ldm4(u32* r, u32 addr) {
    asm volatile("ldmatrix.sync.aligned.m8n8.x4.shared.b16 {%0,%1,%2,%3}, [%4];"
                 : "=r"(r[0]), "=r"(r[1]), "=r"(r[2]), "=r"(r[3]) : "r"(addr));
}
__device__ __forceinline__ void mma16816(float* d, const u32* a, const u32* b) {
    asm volatile(
        "mma.sync.aligned.m16n8k16.row.col.f32.bf16.bf16.f32 "
        "{%0,%1,%2,%3}, {%4,%5,%6,%7}, {%8,%9}, {%0,%1,%2,%3};"
        : "+f"(d[0]), "+f"(d[1]), "+f"(d[2]), "+f"(d[3])
        : "r"(a[0]), "r"(a[1]), "r"(a[2]), "r"(a[3]), "r"(b[0]), "r"(b[1]));
}

// swizzled byte offset within a [rows][64B] tile; 16B slots, conflict-free
__device__ __forceinline__ u32 aoff(int row, int slot) {
    const int key = (row & 3) ^ ((row >> 2) & 1);
    return (u32)(row * 64 + ((slot ^ key) << 4));
}

// =====================================================================
// K0: pre-split weights into g_wb (transposed [u][k]); also zero g_sum.
// =====================================================================
__global__ void k_prep(const float* __restrict__ kx, const float* __restrict__ kt) {
    const int i = blockIdx.x * 256 + threadIdx.x;   // i = k*32 + u
    const int k = i >> 5, u = i & 31;
    {
        const float w = kx[i];
        const __nv_bfloat16 h = __float2bfloat16_rn(w);
        g_wb[0][u * HH + k] = h;
        g_wb[1][u * HH + k] = __float2bfloat16_rn(w - __bfloat162float(h));
    }
    {
        const float w = kt[i];
        const __nv_bfloat16 h = __float2bfloat16_rn(w);
        g_wb[2][u * HH + k] = h;
        g_wb[3][u * HH + k] = __float2bfloat16_rn(w - __bfloat162float(h));
    }
}

// =====================================================================
// K1 (HMMA): delta = lambd*tanh(x@Wx+bx) + (1-lambd)*tanh(t@Wt+bt)
// CTA = 128 rows, 8 warps (warp = 16 rows x 32 u, both GEMMs).
// bf16 3-term split per GEMM. K chunks of 32; smem 40KB static; 2 CTAs/SM.
// =====================================================================
__global__ void __launch_bounds__(256, 2)
k_delta(const float* __restrict__ x, const float* __restrict__ t,
        const float* __restrict__ bx, const float* __restrict__ bt,
        const float* __restrict__ lambd)
{
    __shared__ __align__(16) char sA[4][128 * 64];  // xh, xl, th, tl
    __shared__ __align__(16) char sW[4][32 * 64];   // Wxh, Wxl, Wth, Wtl

    const int tid = threadIdx.x;
    const int wid = tid >> 5;
    const int lane = tid & 31;
    const int rowBase = blockIdx.x * 128;

    if (blockIdx.x < 64) g_sum[blockIdx.x * 256 + tid] = 0.0f;

    const u32 sAa = (u32)__cvta_generic_to_shared(&sA[0][0]);
    const u32 sWa = (u32)__cvta_generic_to_shared(&sW[0][0]);

    float accG[4][4], accB[4][4];
#pragma unroll
    for (int j = 0; j < 4; j++)
#pragma unroll
        for (int q = 0; q < 4; q++) { accG[j][q] = 0.0f; accB[j][q] = 0.0f; }

    // staging roles
    const int arow = tid >> 2;          // 0..63 (+64 on pass 1)
    const int akq = tid & 3;            // 16B slot (8 k)
    // A-frag addresses (per tensor, add s later)
    const int frow = wid * 16 + (lane & 15);
    const int fc0 = (lane >> 4);        // +2s
    // B-frag addresses
    const int bu = ((lane >> 4) & 1) * 8 + (lane & 7);   // +16*nh
    const int bc0 = ((lane >> 3) & 1);                   // +2s

    for (int c = 0; c < 16; c++) {
        // ---- batched LDG ----
        float4 xv[2][2], tv[2][2];
#pragma unroll
        for (int p = 0; p < 2; p++) {
            const size_t go = (size_t)(rowBase + arow + 64 * p) * HH + c * 32 + akq * 8;
            xv[p][0] = *(const float4*)(x + go);
            xv[p][1] = *(const float4*)(x + go + 4);
            tv[p][0] = *(const float4*)(t + go);
            tv[p][1] = *(const float4*)(t + go + 4);
        }
        uint4 wunit[2];
#pragma unroll
        for (int p = 0; p < 2; p++) {
            const int i = tid + 256 * p;               // 0..511
            const int ts = i >> 7, wu = (i >> 2) & 31, wk = i & 3;
            wunit[p] = ((const uint4*)g_wb)[ts * 2048 + wu * 64 + c * 4 + wk];
        }

        __syncthreads();   // previous chunk's compute done

        // ---- STS (swizzled) ----
#pragma unroll
        for (int p = 0; p < 2; p++) {
            const u32 da = aoff(arow + 64 * p, akq);
            uint4 hi, lo;
            split8(xv[p][0], xv[p][1], hi, lo);
            *(uint4*)(sA[0] + da) = hi;
            *(uint4*)(sA[1] + da) = lo;
            split8(tv[p][0], tv[p][1], hi, lo);
            *(uint4*)(sA[2] + da) = hi;
            *(uint4*)(sA[3] + da) = lo;
        }
#pragma unroll
        for (int p = 0; p < 2; p++) {
            const int i = tid + 256 * p;
            const int ts = i >> 7, wu = (i >> 2) & 31, wk = i & 3;
            *(uint4*)(sW[ts] + aoff(wu, wk)) = wunit[p];
        }
        __syncthreads();

        // ---- compute: 2 k16-steps ----
#pragma unroll
        for (int s = 0; s < 2; s++) {
            const u32 offA = aoff(frow, fc0 + 2 * s);
            const u32 offB0 = aoff(bu, bc0 + 2 * s);
            const u32 offB1 = aoff(bu + 16, bc0 + 2 * s);

            u32 ah[4], al[4], bh[8], bl[8];
            // gamma side: x vs Wx
            ldm4(ah, sAa + 0 * 8192 + offA);
            ldm4(al, sAa + 1 * 8192 + offA);
            ldm4(bh + 0, sWa + 0 * 2048 + offB0);
            ldm4(bh + 4, sWa + 0 * 2048 + offB1);
            ldm4(bl + 0, sWa + 1 * 2048 + offB0);
            ldm4(bl + 4, sWa + 1 * 2048 + offB1);
#pragma unroll
            for (int j = 0; j < 4; j++) {
                mma16816(accG[j], ah, bh + 2 * j);
                mma16816(accG[j], ah, bl + 2 * j);
                mma16816(accG[j], al, bh + 2 * j);
            }
            // beta side: t vs Wt
            ldm4(ah, sAa + 2 * 8192 + offA);
            ldm4(al, sAa + 3 * 8192 + offA);
            ldm4(bh + 0, sWa + 2 * 2048 + offB0);
            ldm4(bh + 4, sWa + 2 * 2048 + offB1);
            ldm4(bl + 0, sWa + 3 * 2048 + offB0);
            ldm4(bl + 4, sWa + 3 * 2048 + offB1);
#pragma unroll
            for (int j = 0; j < 4; j++) {
                mma16816(accB[j], ah, bh + 2 * j);
                mma16816(accB[j], ah, bl + 2 * j);
                mma16816(accB[j], al, bh + 2 * j);
            }
        }
    }

    // ---- epilogue: bias + tanh + lambda combine -> g_delta ----
    const int rowL = rowBase + wid * 16 + (lane >> 2);
    const int rowH = rowL + 8;
    const float lamL = __ldg(lambd + (rowL & (TT - 1)));
    const float lamH = __ldg(lambd + (rowH & (TT - 1)));
#pragma unroll
    for (int j = 0; j < 4; j++) {
        const int u0 = j * 8 + (lane & 3) * 2;
        const float bx0 = __ldg(bx + u0), bx1 = __ldg(bx + u0 + 1);
        const float bt0 = __ldg(bt + u0), bt1 = __ldg(bt + u0 + 1);
        float2 oL, oH;
        oL.x = lamL * fast_tanh(accG[j][0] + bx0) + (1.0f - lamL) * fast_tanh(accB[j][0] + bt0);
        oL.y = lamL * fast_tanh(accG[j][1] + bx1) + (1.0f - lamL) * fast_tanh(accB[j][1] + bt1);
        oH.x = lamH * fast_tanh(accG[j][2] + bx0) + (1.0f - lamH) * fast_tanh(accB[j][2] + bt0);
        oH.y = lamH * fast_tanh(accG[j][3] + bx1) + (1.0f - lamH) * fast_tanh(accB[j][3] + bt1);
        *(float2*)(g_delta + (size_t)rowL * UU + u0) = oL;
        *(float2*)(g_delta + (size_t)rowH * UU + u0) = oH;
    }
}

// =====================================================================
// K2: e = exp(delta @ Wa) -> d_out, plus per-(b,h) sums of e. (unchanged)
// =====================================================================
#define K2_SMEM (UU*256*8 + HH*4)   // 67584

__global__ void __launch_bounds__(256, 1)
k_scores(const float* __restrict__ ka, float* __restrict__ out) {
    extern __shared__ char smem[];
    u64t* sWa2 = (u64t*)smem;
    float* ssum = (float*)(smem + UU * 256 * 8);

    const int tid = threadIdx.x;
    const int lane = tid & 31;
    const int w = tid >> 5;

    for (int i = tid; i < UU * 256; i += 256) {
        const int u = i >> 8, hp = i & 255;
        const float2 wv = *(const float2*)(ka + (size_t)u * HH + 2 * hp);
        sWa2[i] = pack2(wv.x, wv.y);
    }
    for (int i = tid; i < HH; i += 256) ssum[i] = 0.0f;
    __syncthreads();

    const int row0 = blockIdx.x * 64 + w * 8;

    float d[8];
#pragma unroll
    for (int r = 0; r < 8; r++)
        d[r] = g_delta[(size_t)(row0 + r) * UU + lane];

    u64t acc[8][8];
#pragma unroll
    for (int r = 0; r < 8; r++)
#pragma unroll
        for (int j = 0; j < 8; j++) acc[r][j] = 0ull;

#pragma unroll 4
    for (int u = 0; u < UU; u++) {
        u64t dd[8];
#pragma unroll
        for (int r = 0; r < 8; r++)
            dd[r] = dup2(__shfl_sync(0xffffffffu, d[r], u));
        const u64t* wrow = sWa2 + u * 256 + lane;
        u64t wv[8];
#pragma unroll
        for (int j = 0; j < 8; j++) wv[j] = wrow[j * 32];
#pragma unroll
        for (int r = 0; r < 8; r++)
#pragma unroll
            for (int j = 0; j < 8; j++)
                ffma2(acc[r][j], dd[r], wv[j]);
    }

    float sx[8], sy[8];
#pragma unroll
    for (int j = 0; j < 8; j++) { sx[j] = 0.0f; sy[j] = 0.0f; }

#pragma unroll
    for (int r = 0; r < 8; r++) {
        float* orow = out + (size_t)(row0 + r) * HH;
#pragma unroll
        for (int j = 0; j < 8; j++) {
            const float2 v = unpack2(acc[r][j]);
            const float e0 = __expf(v.x);
            const float e1 = __expf(v.y);
            *(float2*)(orow + 2 * (lane + 32 * j)) = make_float2(e0, e1);
            sx[j] += e0; sy[j] += e1;
        }
    }

#pragma unroll
    for (int j = 0; j < 8; j++) {
        atomicAdd(&ssum[2 * (lane + 32 * j)], sx[j]);
        atomicAdd(&ssum[2 * (lane + 32 * j) + 1], sy[j]);
    }
    __syncthreads();

    const int b = blockIdx.x >> 5;
    for (int i = tid; i < HH; i += 256)
        atomicAdd(&g_sum[b * HH + i], ssum[i]);
}

// =====================================================================
// K3: alpha = e / sum. (unchanged)
// =====================================================================
__global__ void __launch_bounds__(256)
k_norm(float* __restrict__ out) {
    __shared__ float sinv[HH];
    const int tid = threadIdx.x;
    const int b = blockIdx.x >> 8;
    sinv[tid]       = 1.0f / g_sum[b * HH + tid];
    sinv[tid + 256] = 1.0f / g_sum[b * HH + tid + 256];
    __syncthreads();

    float4* o4 = (float4*)out + (size_t)blockIdx.x * 1024;
#pragma unroll
    for (int j = 0; j < 4; j++) {
        const int i4 = j * 256 + tid;
        float4 e = o4[i4];
        const float4 inv = *(const float4*)(sinv + ((i4 * 4) & (HH - 1)));
        e.x *= inv.x; e.y *= inv.y; e.z *= inv.z; e.w *= inv.w;
        o4[i4] = e;
    }
}

// =====================================================================
extern "C" void kernel_launch(void* const* d_in, const int* in_sizes, int n_in,
                              void* d_out, int out_size) {
    const float* x     = (const float*)d_in[0];
    const float* t     = (const float*)d_in[1];
    const float* kx    = (const float*)d_in[2];
    const float* kt    = (const float*)d_in[3];
    const float* ka    = (const float*)d_in[4];
    const float* bx    = (const float*)d_in[5];
    const float* bt    = (const float*)d_in[6];
    const float* lambd = (const float*)d_in[7];
    float* out = (float*)d_out;

    cudaFuncSetAttribute(k_scores, cudaFuncAttributeMaxDynamicSharedMemorySize, K2_SMEM);

    k_prep<<<HH * UU / 256, 256>>>(kx, kt);
    k_delta<<<ROWS / 128, 256>>>(x, t, bx, bt, lambd);
    k_scores<<<ROWS / 64, 256, K2_SMEM>>>(ka, out);
    k_norm<<<ROWS / 8, 256>>>(out);
}

// round 10
// speedup vs baseline: 2.2634x; 1.1050x over previous
#include <cuda_runtime.h>
#include <cuda_bf16.h>
#include <math.h>
#include <stdint.h>

#define BB 32
#define TT 2048
#define HH 512
#define UU 32
#define ROWS (BB*TT)   // 65536

typedef unsigned long long u64t;
typedef unsigned int u32;

__device__ float g_sum[BB * HH];
// delta split: [row][u] bf16, hi + lo residual (4 MB each)
__device__ __align__(16) __nv_bfloat16 g_dhi[(size_t)ROWS * UU];
__device__ __align__(16) __nv_bfloat16 g_dlo[(size_t)ROWS * UU];
// pre-split transposed weights: [tensor][u][k] bf16; 0=Wxh 1=Wxl 2=Wth 3=Wtl
__device__ __align__(16) __nv_bfloat16 g_wb[4][UU * HH];   // 128 KB
// pre-split transposed Wa: [h][u] bf16 (hi, lo)
__device__ __align__(16) __nv_bfloat16 g_wa[2][HH * UU];   // 64 KB

// ---------------- helpers ----------------
__device__ __forceinline__ float fast_tanh(float a) {
    return 1.0f - 2.0f / (__expf(2.0f * a) + 1.0f);
}
__device__ __forceinline__ u32 b2u(__nv_bfloat162 h) { return *reinterpret_cast<u32*>(&h); }

__device__ __forceinline__ void split8(float4 a, float4 b, uint4& hi, uint4& lo) {
    __nv_bfloat162 h0 = __float22bfloat162_rn(make_float2(a.x, a.y));
    __nv_bfloat162 h1 = __float22bfloat162_rn(make_float2(a.z, a.w));
    __nv_bfloat162 h2 = __float22bfloat162_rn(make_float2(b.x, b.y));
    __nv_bfloat162 h3 = __float22bfloat162_rn(make_float2(b.z, b.w));
    float2 f0 = __bfloat1622float2(h0), f1 = __bfloat1622float2(h1);
    float2 f2 = __bfloat1622float2(h2), f3 = __bfloat1622float2(h3);
    hi = make_uint4(b2u(h0), b2u(h1), b2u(h2), b2u(h3));
    lo = make_uint4(
        b2u(__float22bfloat162_rn(make_float2(a.x - f0.x, a.y - f0.y))),
        b2u(__float22bfloat162_rn(make_float2(a.z - f1.x, a.w - f1.y))),
        b2u(__float22bfloat162_rn(make_float2(b.x - f2.x, b.y - f2.y))),
        b2u(__float22bfloat162_rn(make_float2(b.z - f3.x, b.w - f3.y))));
}

__device__ __forceinline__ void ldm4(u32* r, u32 addr) {
    asm volatile("ldmatrix.sync.aligned.m8n8.x4.shared.b16 {%0,%1,%2,%3}, [%4];"
                 : "=r"(r[0]), "=r"(r[1]), "=r"(r[2]), "=r"(r[3]) : "r"(addr));
}
__device__ __forceinline__ void mma16816(float* d, const u32* a, const u32* b) {
    asm volatile(
        "mma.sync.aligned.m16n8k16.row.col.f32.bf16.bf16.f32 "
        "{%0,%1,%2,%3}, {%4,%5,%6,%7}, {%8,%9}, {%0,%1,%2,%3};"
        : "+f"(d[0]), "+f"(d[1]), "+f"(d[2]), "+f"(d[3])
        : "r"(a[0]), "r"(a[1]), "r"(a[2]), "r"(a[3]), "r"(b[0]), "r"(b[1]));
}

// k_delta A/W tile swizzle: [rows][64B], 16B slots
__device__ __forceinline__ u32 aoff(int row, int slot) {
    const int key = (row & 3) ^ ((row >> 2) & 1);
    return (u32)(row * 64 + ((slot ^ key) << 4));
}
// k_scores tile swizzle: [rows][64B], conflict-free for LDSM phases
__device__ __forceinline__ u32 soff(int r, int slot) {
    return (u32)(r * 64 + ((slot ^ ((r >> 1) & 3)) << 4));
}

// =====================================================================
// K0: pre-split weights (Wx, Wt transposed [u][k]; Wa transposed [h][u])
// =====================================================================
__global__ void k_prep(const float* __restrict__ kx, const float* __restrict__ kt,
                       const float* __restrict__ ka) {
    const int i = blockIdx.x * 256 + threadIdx.x;   // 0..16383
    {   // kx/kt: i = k*32 + u
        const int k = i >> 5, u = i & 31;
        float w = kx[i];
        __nv_bfloat16 h = __float2bfloat16_rn(w);
        g_wb[0][u * HH + k] = h;
        g_wb[1][u * HH + k] = __float2bfloat16_rn(w - __bfloat162float(h));
        w = kt[i];
        h = __float2bfloat16_rn(w);
        g_wb[2][u * HH + k] = h;
        g_wb[3][u * HH + k] = __float2bfloat16_rn(w - __bfloat162float(h));
    }
    {   // ka: i = u*512 + h  ->  g_wa[.][h*32 + u]
        const int u = i >> 9, h = i & 511;
        const float w = ka[i];
        const __nv_bfloat16 hb = __float2bfloat16_rn(w);
        g_wa[0][h * UU + u] = hb;
        g_wa[1][h * UU + u] = __float2bfloat16_rn(w - __bfloat162float(hb));
    }
}

// =====================================================================
// K1 (HMMA): delta = lambd*tanh(x@Wx+bx) + (1-lambd)*tanh(t@Wt+bt)
// -> stored as bf16 hi/lo. CTA = 128 rows, 8 warps, 3-term bf16 split.
// =====================================================================
__global__ void __launch_bounds__(256, 2)
k_delta(const float* __restrict__ x, const float* __restrict__ t,
        const float* __restrict__ bx, const float* __restrict__ bt,
        const float* __restrict__ lambd)
{
    __shared__ __align__(16) char sA[4][128 * 64];  // xh, xl, th, tl
    __shared__ __align__(16) char sW[4][32 * 64];   // Wxh, Wxl, Wth, Wtl

    const int tid = threadIdx.x;
    const int wid = tid >> 5;
    const int lane = tid & 31;
    const int rowBase = blockIdx.x * 128;

    if (blockIdx.x < 64) g_sum[blockIdx.x * 256 + tid] = 0.0f;

    const u32 sAa = (u32)__cvta_generic_to_shared(&sA[0][0]);
    const u32 sWa = (u32)__cvta_generic_to_shared(&sW[0][0]);

    float accG[4][4], accB[4][4];
#pragma unroll
    for (int j = 0; j < 4; j++)
#pragma unroll
        for (int q = 0; q < 4; q++) { accG[j][q] = 0.0f; accB[j][q] = 0.0f; }

    const int arow = tid >> 2;
    const int akq = tid & 3;
    const int frow = wid * 16 + (lane & 15);
    const int fc0 = (lane >> 4);
    const int bu = ((lane >> 4) & 1) * 8 + (lane & 7);
    const int bc0 = ((lane >> 3) & 1);

    for (int c = 0; c < 16; c++) {
        float4 xv[2][2], tv[2][2];
#pragma unroll
        for (int p = 0; p < 2; p++) {
            const size_t go = (size_t)(rowBase + arow + 64 * p) * HH + c * 32 + akq * 8;
            xv[p][0] = *(const float4*)(x + go);
            xv[p][1] = *(const float4*)(x + go + 4);
            tv[p][0] = *(const float4*)(t + go);
            tv[p][1] = *(const float4*)(t + go + 4);
        }
        uint4 wunit[2];
#pragma unroll
        for (int p = 0; p < 2; p++) {
            const int i = tid + 256 * p;
            const int ts = i >> 7, wu = (i >> 2) & 31, wk = i & 3;
            wunit[p] = ((const uint4*)g_wb)[ts * 2048 + wu * 64 + c * 4 + wk];
        }

        __syncthreads();

#pragma unroll
        for (int p = 0; p < 2; p++) {
            const u32 da = aoff(arow + 64 * p, akq);
            uint4 hi, lo;
            split8(xv[p][0], xv[p][1], hi, lo);
            *(uint4*)(sA[0] + da) = hi;
            *(uint4*)(sA[1] + da) = lo;
            split8(tv[p][0], tv[p][1], hi, lo);
            *(uint4*)(sA[2] + da) = hi;
            *(uint4*)(sA[3] + da) = lo;
        }
#pragma unroll
        for (int p = 0; p < 2; p++) {
            const int i = tid + 256 * p;
            const int ts = i >> 7, wu = (i >> 2) & 31, wk = i & 3;
            *(uint4*)(sW[ts] + aoff(wu, wk)) = wunit[p];
        }
        __syncthreads();

#pragma unroll
        for (int s = 0; s < 2; s++) {
            const u32 offA = aoff(frow, fc0 + 2 * s);
            const u32 offB0 = aoff(bu, bc0 + 2 * s);
            const u32 offB1 = aoff(bu + 16, bc0 + 2 * s);

            u32 ah[4], al[4], bh[8], bl[8];
            ldm4(ah, sAa + 0 * 8192 + offA);
            ldm4(al, sAa + 1 * 8192 + offA);
            ldm4(bh + 0, sWa + 0 * 2048 + offB0);
            ldm4(bh + 4, sWa + 0 * 2048 + offB1);
            ldm4(bl + 0, sWa + 1 * 2048 + offB0);
            ldm4(bl + 4, sWa + 1 * 2048 + offB1);
#pragma unroll
            for (int j = 0; j < 4; j++) {
                mma16816(accG[j], ah, bh + 2 * j);
                mma16816(accG[j], ah, bl + 2 * j);
                mma16816(accG[j], al, bh + 2 * j);
            }
            ldm4(ah, sAa + 2 * 8192 + offA);
            ldm4(al, sAa + 3 * 8192 + offA);
            ldm4(bh + 0, sWa + 2 * 2048 + offB0);
            ldm4(bh + 4, sWa + 2 * 2048 + offB1);
            ldm4(bl + 0, sWa + 3 * 2048 + offB0);
            ldm4(bl + 4, sWa + 3 * 2048 + offB1);
#pragma unroll
            for (int j = 0; j < 4; j++) {
                mma16816(accB[j], ah, bh + 2 * j);
                mma16816(accB[j], ah, bl + 2 * j);
                mma16816(accB[j], al, bh + 2 * j);
            }
        }
    }

    // epilogue: bias + tanh + lambda combine -> g_dhi/g_dlo (bf16 split)
    const int rowL = rowBase + wid * 16 + (lane >> 2);
    const int rowH = rowL + 8;
    const float lamL = __ldg(lambd + (rowL & (TT - 1)));
    const float lamH = __ldg(lambd + (rowH & (TT - 1)));
#pragma unroll
    for (int j = 0; j < 4; j++) {
        const int u0 = j * 8 + (lane & 3) * 2;
        const float bx0 = __ldg(bx + u0), bx1 = __ldg(bx + u0 + 1);
        const float bt0 = __ldg(bt + u0), bt1 = __ldg(bt + u0 + 1);
        float2 oL, oH;
        oL.x = lamL * fast_tanh(accG[j][0] + bx0) + (1.0f - lamL) * fast_tanh(accB[j][0] + bt0);
        oL.y = lamL * fast_tanh(accG[j][1] + bx1) + (1.0f - lamL) * fast_tanh(accB[j][1] + bt1);
        oH.x = lamH * fast_tanh(accG[j][2] + bx0) + (1.0f - lamH) * fast_tanh(accB[j][2] + bt0);
        oH.y = lamH * fast_tanh(accG[j][3] + bx1) + (1.0f - lamH) * fast_tanh(accB[j][3] + bt1);

        __nv_bfloat162 h2 = __float22bfloat162_rn(oL);
        float2 hf = __bfloat1622float2(h2);
        *(__nv_bfloat162*)(g_dhi + (size_t)rowL * UU + u0) = h2;
        *(__nv_bfloat162*)(g_dlo + (size_t)rowL * UU + u0) =
            __float22bfloat162_rn(make_float2(oL.x - hf.x, oL.y - hf.y));
        h2 = __float22bfloat162_rn(oH);
        hf = __bfloat1622float2(h2);
        *(__nv_bfloat162*)(g_dhi + (size_t)rowH * UU + u0) = h2;
        *(__nv_bfloat162*)(g_dlo + (size_t)rowH * UU + u0) =
            __float22bfloat162_rn(make_float2(oH.x - hf.x, oH.y - hf.y));
    }
}

// =====================================================================
// K2 (HMMA): e = exp(delta @ Wa) -> d_out, per-(b,h) sums -> g_sum.
// CTA = 64 rows, 512 threads, 16 warps (warp = 16 rows x 128 h).
// 3-term bf16 split: dh@Wh + dh@Wl + dl@Wh, fp32 acc. Max-sub skipped.
// =====================================================================
#define K2S_BH 0
#define K2S_BL 32768
#define K2S_AH 65536
#define K2S_AL 69632
#define K2S_SUM 73728
#define K2_SMEM (K2S_SUM + HH*4)   // 75776

__global__ void __launch_bounds__(512, 1)
k_scores(float* __restrict__ out) {
    extern __shared__ char smem[];
    const u32 sb = (u32)__cvta_generic_to_shared(smem);
    float* ssum = (float*)(smem + K2S_SUM);

    const int tid = threadIdx.x;
    const int lane = tid & 31;
    const int wid = tid >> 5;
    const int rowBase = blockIdx.x * 64;

    // stage B (Wa hi/lo, [h][32u] bf16, swizzled)
#pragma unroll
    for (int p = 0; p < 4; p++) {
        const int i = tid + 512 * p;          // 0..2047
        const int h = i >> 2, sl = i & 3;
        const u32 d = soff(h, sl);
        *(uint4*)(smem + K2S_BH + d) = *(const uint4*)((const char*)g_wa[0] + h * 64 + sl * 16);
        *(uint4*)(smem + K2S_BL + d) = *(const uint4*)((const char*)g_wa[1] + h * 64 + sl * 16);
    }
    // stage A (delta hi/lo for 64 rows)
    {
        const int i = tid & 255;
        const int r = i >> 2, sl = i & 3;
        const u32 d = soff(r, sl);
        const size_t go = (size_t)(rowBase + r) * 64 + sl * 16;
        if (tid < 256)
            *(uint4*)(smem + K2S_AH + d) = *(const uint4*)((const char*)g_dhi + go);
        else
            *(uint4*)(smem + K2S_AL + d) = *(const uint4*)((const char*)g_dlo + go);
    }
    ssum[tid] = 0.0f;
    __syncthreads();

    const int g = lane >> 3, l = lane & 7;
    const int rt = wid & 3;       // row tile (16 rows)
    const int hq = wid >> 2;      // h quarter (128 h)

    float acc[16][4];
#pragma unroll
    for (int n = 0; n < 16; n++)
#pragma unroll
        for (int q = 0; q < 4; q++) acc[n][q] = 0.0f;

#pragma unroll
    for (int s = 0; s < 2; s++) {
        u32 ah[4], al[4];
        const u32 ao = soff(rt * 16 + (g & 1) * 8 + l, 2 * s + (g >> 1));
        ldm4(ah, sb + K2S_AH + ao);
        ldm4(al, sb + K2S_AL + ao);
#pragma unroll
        for (int nt = 0; nt < 8; nt++) {
            const int h0 = hq * 128 + nt * 16;
            const u32 bo = soff(h0 + (g >> 1) * 8 + l, 2 * s + (g & 1));
            u32 bh[4], bl[4];
            ldm4(bh, sb + K2S_BH + bo);
            ldm4(bl, sb + K2S_BL + bo);
            mma16816(acc[2 * nt],     ah, bh);
            mma16816(acc[2 * nt],     ah, bl);
            mma16816(acc[2 * nt],     al, bh);
            mma16816(acc[2 * nt + 1], ah, bh + 2);
            mma16816(acc[2 * nt + 1], ah, bl + 2);
            mma16816(acc[2 * nt + 1], al, bh + 2);
        }
    }

    // epilogue: exp, store, row-sum reduce
    const int rowL = rowBase + rt * 16 + (lane >> 2);
    float* oL = out + (size_t)rowL * HH;
    float* oH = oL + 8 * HH;
#pragma unroll
    for (int n8 = 0; n8 < 16; n8++) {
        const int h = hq * 128 + n8 * 8 + (lane & 3) * 2;
        const float e00 = __expf(acc[n8][0]), e01 = __expf(acc[n8][1]);
        const float e10 = __expf(acc[n8][2]), e11 = __expf(acc[n8][3]);
        *(float2*)(oL + h) = make_float2(e00, e01);
        *(float2*)(oH + h) = make_float2(e10, e11);
        float s0 = e00 + e10, s1 = e01 + e11;
        s0 += __shfl_xor_sync(0xffffffffu, s0, 4);
        s0 += __shfl_xor_sync(0xffffffffu, s0, 8);
        s0 += __shfl_xor_sync(0xffffffffu, s0, 16);
        s1 += __shfl_xor_sync(0xffffffffu, s1, 4);
        s1 += __shfl_xor_sync(0xffffffffu, s1, 8);
        s1 += __shfl_xor_sync(0xffffffffu, s1, 16);
        if (lane < 4) {
            atomicAdd(&ssum[h], s0);
            atomicAdd(&ssum[h + 1], s1);
        }
    }
    __syncthreads();

    const int b = blockIdx.x >> 5;   // 32 blocks (64 rows) per batch
    atomicAdd(&g_sum[b * HH + tid], ssum[tid]);
}

// =====================================================================
// K3: alpha = e / sum. (unchanged)
// =====================================================================
__global__ void __launch_bounds__(256)
k_norm(float* __restrict__ out) {
    __shared__ float sinv[HH];
    const int tid = threadIdx.x;
    const int b = blockIdx.x >> 8;
    sinv[tid]       = 1.0f / g_sum[b * HH + tid];
    sinv[tid + 256] = 1.0f / g_sum[b * HH + tid + 256];
    __syncthreads();

    float4* o4 = (float4*)out + (size_t)blockIdx.x * 1024;
#pragma unroll
    for (int j = 0; j < 4; j++) {
        const int i4 = j * 256 + tid;
        float4 e = o4[i4];
        const float4 inv = *(const float4*)(sinv + ((i4 * 4) & (HH - 1)));
        e.x *= inv.x; e.y *= inv.y; e.z *= inv.z; e.w *= inv.w;
        o4[i4] = e;
    }
}

// =====================================================================
extern "C" void kernel_launch(void* const* d_in, const int* in_sizes, int n_in,
                              void* d_out, int out_size) {
    const float* x     = (const float*)d_in[0];
    const float* t     = (const float*)d_in[1];
    const float* kx    = (const float*)d_in[2];
    const float* kt    = (const float*)d_in[3];
    const float* ka    = (const float*)d_in[4];
    const float* bx    = (const float*)d_in[5];
    const float* bt    = (const float*)d_in[6];
    const float* lambd = (const float*)d_in[7];
    float* out = (float*)d_out;

    cudaFuncSetAttribute(k_scores, cudaFuncAttributeMaxDynamicSharedMemorySize, K2_SMEM);

    k_prep<<<HH * UU / 256, 256>>>(kx, kt, ka);
    k_delta<<<ROWS / 128, 256>>>(x, t, bx, bt, lambd);
    k_scores<<<ROWS / 64, 512, K2_SMEM>>>(out);
    k_norm<<<ROWS / 8, 256>>>(out);
}

// round 11
// speedup vs baseline: 2.4558x; 1.0850x over previous
#include <cuda_runtime.h>
#include <cuda_bf16.h>
#include <math.h>
#include <stdint.h>

#define BB 32
#define TT 2048
#define HH 512
#define UU 32
#define ROWS (BB*TT)   // 65536

typedef unsigned int u32;

__device__ float g_sum[BB * HH];
// delta split: [row][u] bf16, hi + lo residual (4 MB each)
__device__ __align__(16) __nv_bfloat16 g_dhi[(size_t)ROWS * UU];
__device__ __align__(16) __nv_bfloat16 g_dlo[(size_t)ROWS * UU];
// pre-split transposed weights: [tensor][u][k] bf16; 0=Wxh 1=Wxl 2=Wth 3=Wtl
__device__ __align__(16) __nv_bfloat16 g_wb[4][UU * HH];   // 128 KB
// pre-split transposed Wa: [h][u] bf16 (hi, lo)
__device__ __align__(16) __nv_bfloat16 g_wa[2][HH * UU];   // 64 KB

// ---------------- helpers ----------------
__device__ __forceinline__ float fast_tanh(float a) {
    return 1.0f - 2.0f / (__expf(2.0f * a) + 1.0f);
}
__device__ __forceinline__ u32 b2u(__nv_bfloat162 h) { return *reinterpret_cast<u32*>(&h); }

__device__ __forceinline__ void split8(float4 a, float4 b, uint4& hi, uint4& lo) {
    __nv_bfloat162 h0 = __float22bfloat162_rn(make_float2(a.x, a.y));
    __nv_bfloat162 h1 = __float22bfloat162_rn(make_float2(a.z, a.w));
    __nv_bfloat162 h2 = __float22bfloat162_rn(make_float2(b.x, b.y));
    __nv_bfloat162 h3 = __float22bfloat162_rn(make_float2(b.z, b.w));
    float2 f0 = __bfloat1622float2(h0), f1 = __bfloat1622float2(h1);
    float2 f2 = __bfloat1622float2(h2), f3 = __bfloat1622float2(h3);
    hi = make_uint4(b2u(h0), b2u(h1), b2u(h2), b2u(h3));
    lo = make_uint4(
        b2u(__float22bfloat162_rn(make_float2(a.x - f0.x, a.y - f0.y))),
        b2u(__float22bfloat162_rn(make_float2(a.z - f1.x, a.w - f1.y))),
        b2u(__float22bfloat162_rn(make_float2(b.x - f2.x, b.y - f2.y))),
        b2u(__float22bfloat162_rn(make_float2(b.z - f3.x, b.w - f3.y))));
}

__device__ __forceinline__ void ldm4(u32* r, u32 addr) {
    asm volatile("ldmatrix.sync.aligned.m8n8.x4.shared.b16 {%0,%1,%2,%3}, [%4];"
                 : "=r"(r[0]), "=r"(r[1]), "=r"(r[2]), "=r"(r[3]) : "r"(addr));
}
__device__ __forceinline__ void mma16816(float* d, const u32* a, const u32* b) {
    asm volatile(
        "mma.sync.aligned.m16n8k16.row.col.f32.bf16.bf16.f32 "
        "{%0,%1,%2,%3}, {%4,%5,%6,%7}, {%8,%9}, {%0,%1,%2,%3};"
        : "+f"(d[0]), "+f"(d[1]), "+f"(d[2]), "+f"(d[3])
        : "r"(a[0]), "r"(a[1]), "r"(a[2]), "r"(a[3]), "r"(b[0]), "r"(b[1]));
}

// k_delta A/W tile swizzle: [rows][64B], 16B slots
__device__ __forceinline__ u32 aoff(int row, int slot) {
    const int key = (row & 3) ^ ((row >> 2) & 1);
    return (u32)(row * 64 + ((slot ^ key) << 4));
}
// scores tile swizzle: [rows][64B], conflict-free for LDSM phases
__device__ __forceinline__ u32 soff(int r, int slot) {
    return (u32)(r * 64 + ((slot ^ ((r >> 1) & 3)) << 4));
}

// =====================================================================
// K0: pre-split weights (Wx, Wt transposed [u][k]; Wa transposed [h][u])
// =====================================================================
__global__ void k_prep(const float* __restrict__ kx, const float* __restrict__ kt,
                       const float* __restrict__ ka) {
    const int i = blockIdx.x * 256 + threadIdx.x;   // 0..16383
    {   // kx/kt: i = k*32 + u
        const int k = i >> 5, u = i & 31;
        float w = kx[i];
        __nv_bfloat16 h = __float2bfloat16_rn(w);
        g_wb[0][u * HH + k] = h;
        g_wb[1][u * HH + k] = __float2bfloat16_rn(w - __bfloat162float(h));
        w = kt[i];
        h = __float2bfloat16_rn(w);
        g_wb[2][u * HH + k] = h;
        g_wb[3][u * HH + k] = __float2bfloat16_rn(w - __bfloat162float(h));
    }
    {   // ka: i = u*512 + h  ->  g_wa[.][h*32 + u]
        const int u = i >> 9, h = i & 511;
        const float w = ka[i];
        const __nv_bfloat16 hb = __float2bfloat16_rn(w);
        g_wa[0][h * UU + u] = hb;
        g_wa[1][h * UU + u] = __float2bfloat16_rn(w - __bfloat162float(hb));
    }
}

// =====================================================================
// K1 (HMMA): delta = lambd*tanh(x@Wx+bx) + (1-lambd)*tanh(t@Wt+bt)
// -> stored as bf16 hi/lo. CTA = 128 rows, 8 warps, 3-term bf16 split.
// =====================================================================
__global__ void __launch_bounds__(256, 2)
k_delta(const float* __restrict__ x, const float* __restrict__ t,
        const float* __restrict__ bx, const float* __restrict__ bt,
        const float* __restrict__ lambd)
{
    __shared__ __align__(16) char sA[4][128 * 64];  // xh, xl, th, tl
    __shared__ __align__(16) char sW[4][32 * 64];   // Wxh, Wxl, Wth, Wtl

    const int tid = threadIdx.x;
    const int wid = tid >> 5;
    const int lane = tid & 31;
    const int rowBase = blockIdx.x * 128;

    if (blockIdx.x < 64) g_sum[blockIdx.x * 256 + tid] = 0.0f;

    const u32 sAa = (u32)__cvta_generic_to_shared(&sA[0][0]);
    const u32 sWa = (u32)__cvta_generic_to_shared(&sW[0][0]);

    float accG[4][4], accB[4][4];
#pragma unroll
    for (int j = 0; j < 4; j++)
#pragma unroll
        for (int q = 0; q < 4; q++) { accG[j][q] = 0.0f; accB[j][q] = 0.0f; }

    const int arow = tid >> 2;
    const int akq = tid & 3;
    const int frow = wid * 16 + (lane & 15);
    const int fc0 = (lane >> 4);
    const int bu = ((lane >> 4) & 1) * 8 + (lane & 7);
    const int bc0 = ((lane >> 3) & 1);

    for (int c = 0; c < 16; c++) {
        float4 xv[2][2], tv[2][2];
#pragma unroll
        for (int p = 0; p < 2; p++) {
            const size_t go = (size_t)(rowBase + arow + 64 * p) * HH + c * 32 + akq * 8;
            xv[p][0] = *(const float4*)(x + go);
            xv[p][1] = *(const float4*)(x + go + 4);
            tv[p][0] = *(const float4*)(t + go);
            tv[p][1] = *(const float4*)(t + go + 4);
        }
        uint4 wunit[2];
#pragma unroll
        for (int p = 0; p < 2; p++) {
            const int i = tid + 256 * p;
            const int ts = i >> 7, wu = (i >> 2) & 31, wk = i & 3;
            wunit[p] = ((const uint4*)g_wb)[ts * 2048 + wu * 64 + c * 4 + wk];
        }

        __syncthreads();

#pragma unroll
        for (int p = 0; p < 2; p++) {
            const u32 da = aoff(arow + 64 * p, akq);
            uint4 hi, lo;
            split8(xv[p][0], xv[p][1], hi, lo);
            *(uint4*)(sA[0] + da) = hi;
            *(uint4*)(sA[1] + da) = lo;
            split8(tv[p][0], tv[p][1], hi, lo);
            *(uint4*)(sA[2] + da) = hi;
            *(uint4*)(sA[3] + da) = lo;
        }
#pragma unroll
        for (int p = 0; p < 2; p++) {
            const int i = tid + 256 * p;
            const int ts = i >> 7, wu = (i >> 2) & 31, wk = i & 3;
            *(uint4*)(sW[ts] + aoff(wu, wk)) = wunit[p];
        }
        __syncthreads();

#pragma unroll
        for (int s = 0; s < 2; s++) {
            const u32 offA = aoff(frow, fc0 + 2 * s);
            const u32 offB0 = aoff(bu, bc0 + 2 * s);
            const u32 offB1 = aoff(bu + 16, bc0 + 2 * s);

            u32 ah[4], al[4], bh[8], bl[8];
            ldm4(ah, sAa + 0 * 8192 + offA);
            ldm4(al, sAa + 1 * 8192 + offA);
            ldm4(bh + 0, sWa + 0 * 2048 + offB0);
            ldm4(bh + 4, sWa + 0 * 2048 + offB1);
            ldm4(bl + 0, sWa + 1 * 2048 + offB0);
            ldm4(bl + 4, sWa + 1 * 2048 + offB1);
#pragma unroll
            for (int j = 0; j < 4; j++) {
                mma16816(accG[j], ah, bh + 2 * j);
                mma16816(accG[j], ah, bl + 2 * j);
                mma16816(accG[j], al, bh + 2 * j);
            }
            ldm4(ah, sAa + 2 * 8192 + offA);
            ldm4(al, sAa + 3 * 8192 + offA);
            ldm4(bh + 0, sWa + 2 * 2048 + offB0);
            ldm4(bh + 4, sWa + 2 * 2048 + offB1);
            ldm4(bl + 0, sWa + 3 * 2048 + offB0);
            ldm4(bl + 4, sWa + 3 * 2048 + offB1);
#pragma unroll
            for (int j = 0; j < 4; j++) {
                mma16816(accB[j], ah, bh + 2 * j);
                mma16816(accB[j], ah, bl + 2 * j);
                mma16816(accB[j], al, bh + 2 * j);
            }
        }
    }

    // epilogue: bias + tanh + lambda combine -> g_dhi/g_dlo (bf16 split)
    const int rowL = rowBase + wid * 16 + (lane >> 2);
    const int rowH = rowL + 8;
    const float lamL = __ldg(lambd + (rowL & (TT - 1)));
    const float lamH = __ldg(lambd + (rowH & (TT - 1)));
#pragma unroll
    for (int j = 0; j < 4; j++) {
        const int u0 = j * 8 + (lane & 3) * 2;
        const float bx0 = __ldg(bx + u0), bx1 = __ldg(bx + u0 + 1);
        const float bt0 = __ldg(bt + u0), bt1 = __ldg(bt + u0 + 1);
        float2 oL, oH;
        oL.x = lamL * fast_tanh(accG[j][0] + bx0) + (1.0f - lamL) * fast_tanh(accB[j][0] + bt0);
        oL.y = lamL * fast_tanh(accG[j][1] + bx1) + (1.0f - lamL) * fast_tanh(accB[j][1] + bt1);
        oH.x = lamH * fast_tanh(accG[j][2] + bx0) + (1.0f - lamH) * fast_tanh(accB[j][2] + bt0);
        oH.y = lamH * fast_tanh(accG[j][3] + bx1) + (1.0f - lamH) * fast_tanh(accB[j][3] + bt1);

        __nv_bfloat162 h2 = __float22bfloat162_rn(oL);
        float2 hf = __bfloat1622float2(h2);
        *(__nv_bfloat162*)(g_dhi + (size_t)rowL * UU + u0) = h2;
        *(__nv_bfloat162*)(g_dlo + (size_t)rowL * UU + u0) =
            __float22bfloat162_rn(make_float2(oL.x - hf.x, oL.y - hf.y));
        h2 = __float22bfloat162_rn(oH);
        hf = __bfloat1622float2(h2);
        *(__nv_bfloat162*)(g_dhi + (size_t)rowH * UU + u0) = h2;
        *(__nv_bfloat162*)(g_dlo + (size_t)rowH * UU + u0) =
            __float22bfloat162_rn(make_float2(oH.x - hf.x, oH.y - hf.y));
    }
}

// =====================================================================
// shared GEMM core for scores: computes acc[16][4] = delta @ Wa for
// CTA's 64 rows x this warp's 128-h quarter. 512 threads, 16 warps.
// =====================================================================
#define K2S_BH 0
#define K2S_BL 32768
#define K2S_AH 65536
#define K2S_AL 69632
#define K2S_SUM 73728
#define K2_SMEM (K2S_SUM + HH*4)   // 75776

__device__ __forceinline__ void scores_gemm(char* smem, u32 sb, int rowBase,
                                            int tid, float acc[16][4]) {
    // stage B (Wa hi/lo, [h][32u] bf16, swizzled)
#pragma unroll
    for (int p = 0; p < 4; p++) {
        const int i = tid + 512 * p;          // 0..2047
        const int h = i >> 2, sl = i & 3;
        const u32 d = soff(h, sl);
        *(uint4*)(smem + K2S_BH + d) = *(const uint4*)((const char*)g_wa[0] + h * 64 + sl * 16);
        *(uint4*)(smem + K2S_BL + d) = *(const uint4*)((const char*)g_wa[1] + h * 64 + sl * 16);
    }
    // stage A (delta hi/lo for 64 rows)
    {
        const int i = tid & 255;
        const int r = i >> 2, sl = i & 3;
        const u32 d = soff(r, sl);
        const size_t go = (size_t)(rowBase + r) * 64 + sl * 16;
        if (tid < 256)
            *(uint4*)(smem + K2S_AH + d) = *(const uint4*)((const char*)g_dhi + go);
        else
            *(uint4*)(smem + K2S_AL + d) = *(const uint4*)((const char*)g_dlo + go);
    }
    __syncthreads();

    const int lane = tid & 31;
    const int wid = tid >> 5;
    const int g = lane >> 3, l = lane & 7;
    const int rt = wid & 3;
    const int hq = wid >> 2;

#pragma unroll
    for (int s = 0; s < 2; s++) {
        u32 ah[4], al[4];
        const u32 ao = soff(rt * 16 + (g & 1) * 8 + l, 2 * s + (g >> 1));
        ldm4(ah, sb + K2S_AH + ao);
        ldm4(al, sb + K2S_AL + ao);
#pragma unroll
        for (int nt = 0; nt < 8; nt++) {
            const int h0 = hq * 128 + nt * 16;
            const u32 bo = soff(h0 + (g >> 1) * 8 + l, 2 * s + (g & 1));
            u32 bh[4], bl[4];
            ldm4(bh, sb + K2S_BH + bo);
            ldm4(bl, sb + K2S_BL + bo);
            mma16816(acc[2 * nt],     ah, bh);
            mma16816(acc[2 * nt],     ah, bl);
            mma16816(acc[2 * nt],     al, bh);
            mma16816(acc[2 * nt + 1], ah, bh + 2);
            mma16816(acc[2 * nt + 1], ah, bl + 2);
            mma16816(acc[2 * nt + 1], al, bh + 2);
        }
    }
}

// =====================================================================
// K2a: sums only — g_sum[b,h] += sum_rows exp(score). No score stores.
// =====================================================================
__global__ void __launch_bounds__(512, 1)
k_ssum(int dummy) {
    extern __shared__ char smem[];
    const u32 sb = (u32)__cvta_generic_to_shared(smem);
    float* ssum = (float*)(smem + K2S_SUM);

    const int tid = threadIdx.x;
    const int lane = tid & 31;
    const int wid = tid >> 5;
    const int rowBase = blockIdx.x * 64;

    ssum[tid] = 0.0f;

    float acc[16][4];
#pragma unroll
    for (int n = 0; n < 16; n++)
#pragma unroll
        for (int q = 0; q < 4; q++) acc[n][q] = 0.0f;

    scores_gemm(smem, sb, rowBase, tid, acc);

    const int hq = wid >> 2;
#pragma unroll
    for (int n8 = 0; n8 < 16; n8++) {
        const int h = hq * 128 + n8 * 8 + (lane & 3) * 2;
        float s0 = __expf(acc[n8][0]) + __expf(acc[n8][2]);
        float s1 = __expf(acc[n8][1]) + __expf(acc[n8][3]);
        s0 += __shfl_xor_sync(0xffffffffu, s0, 4);
        s0 += __shfl_xor_sync(0xffffffffu, s0, 8);
        s0 += __shfl_xor_sync(0xffffffffu, s0, 16);
        s1 += __shfl_xor_sync(0xffffffffu, s1, 4);
        s1 += __shfl_xor_sync(0xffffffffu, s1, 8);
        s1 += __shfl_xor_sync(0xffffffffu, s1, 16);
        if (lane < 4) {
            atomicAdd(&ssum[h], s0);
            atomicAdd(&ssum[h + 1], s1);
        }
    }
    __syncthreads();

    const int b = blockIdx.x >> 5;   // 32 blocks (64 rows) per batch
    atomicAdd(&g_sum[b * HH + tid], ssum[tid]);
}

// =====================================================================
// K2b: recompute scores, alpha = exp(score)/sum -> out (single write).
// =====================================================================
__global__ void __launch_bounds__(512, 1)
k_norm(float* __restrict__ out) {
    extern __shared__ char smem[];
    const u32 sb = (u32)__cvta_generic_to_shared(smem);
    float* sinv = (float*)(smem + K2S_SUM);

    const int tid = threadIdx.x;
    const int lane = tid & 31;
    const int wid = tid >> 5;
    const int rowBase = blockIdx.x * 64;
    const int b = blockIdx.x >> 5;

    sinv[tid] = 1.0f / g_sum[b * HH + tid];

    float acc[16][4];
#pragma unroll
    for (int n = 0; n < 16; n++)
#pragma unroll
        for (int q = 0; q < 4; q++) acc[n][q] = 0.0f;

    scores_gemm(smem, sb, rowBase, tid, acc);

    const int rt = wid & 3;
    const int hq = wid >> 2;
    const int rowL = rowBase + rt * 16 + (lane >> 2);
    float* oL = out + (size_t)rowL * HH;
    float* oH = oL + 8 * HH;
#pragma unroll
    for (int n8 = 0; n8 < 16; n8++) {
        const int h = hq * 128 + n8 * 8 + (lane & 3) * 2;
        const float2 inv = *(const float2*)(sinv + h);
        *(float2*)(oL + h) = make_float2(__expf(acc[n8][0]) * inv.x,
                                         __expf(acc[n8][1]) * inv.y);
        *(float2*)(oH + h) = make_float2(__expf(acc[n8][2]) * inv.x,
                                         __expf(acc[n8][3]) * inv.y);
    }
}

// =====================================================================
extern "C" void kernel_launch(void* const* d_in, const int* in_sizes, int n_in,
                              void* d_out, int out_size) {
    const float* x     = (const float*)d_in[0];
    const float* t     = (const float*)d_in[1];
    const float* kx    = (const float*)d_in[2];
    const float* kt    = (const float*)d_in[3];
    const float* ka    = (const float*)d_in[4];
    const float* bx    = (const float*)d_in[5];
    const float* bt    = (const float*)d_in[6];
    const float* lambd = (const float*)d_in[7];
    float* out = (float*)d_out;

    cudaFuncSetAttribute(k_ssum, cudaFuncAttributeMaxDynamicSharedMemorySize, K2_SMEM);
    cudaFuncSetAttribute(k_norm, cudaFuncAttributeMaxDynamicSharedMemorySize, K2_SMEM);

    k_prep<<<HH * UU / 256, 256>>>(kx, kt, ka);
    k_delta<<<ROWS / 128, 256>>>(x, t, bx, bt, lambd);
    k_ssum<<<ROWS / 64, 512, K2_SMEM>>>(0);
    k_norm<<<ROWS / 64, 512, K2_SMEM>>>(out);
}

// round 12
// speedup vs baseline: 2.4975x; 1.0170x over previous
#include <cuda_runtime.h>
#include <cuda_bf16.h>
#include <math.h>
#include <stdint.h>

#define BB 32
#define TT 2048
#define HH 512
#define UU 32
#define ROWS (BB*TT)   // 65536

typedef unsigned int u32;

__device__ float g_sum[BB * HH];
// delta split: [row][u] bf16, hi + lo residual (4 MB each)
__device__ __align__(16) __nv_bfloat16 g_dhi[(size_t)ROWS * UU];
__device__ __align__(16) __nv_bfloat16 g_dlo[(size_t)ROWS * UU];
// pre-split transposed weights: [tensor][u][k] bf16; 0=Wxh 1=Wxl 2=Wth 3=Wtl
__device__ __align__(16) __nv_bfloat16 g_wb[4][UU * HH];   // 128 KB
// pre-split transposed Wa: [h][u] bf16 (hi, lo)
__device__ __align__(16) __nv_bfloat16 g_wa[2][HH * UU];   // 64 KB

// ---------------- helpers ----------------
__device__ __forceinline__ float fast_tanh(float a) {
    return 1.0f - 2.0f / (__expf(2.0f * a) + 1.0f);
}
__device__ __forceinline__ u32 b2u(__nv_bfloat162 h) { return *reinterpret_cast<u32*>(&h); }

// split one float2 (consecutive k) into bf16x2 hi + bf16x2 lo (fragment-ready)
__device__ __forceinline__ void cvt2(float2 f, u32& hi, u32& lo) {
    __nv_bfloat162 h = __float22bfloat162_rn(f);
    const u32 hb = *reinterpret_cast<u32*>(&h);
    const float hx = __uint_as_float(hb << 16);
    const float hy = __uint_as_float(hb & 0xffff0000u);
    __nv_bfloat162 l = __float22bfloat162_rn(make_float2(f.x - hx, f.y - hy));
    hi = hb;
    lo = *reinterpret_cast<u32*>(&l);
}

__device__ __forceinline__ void ldm4(u32* r, u32 addr) {
    asm volatile("ldmatrix.sync.aligned.m8n8.x4.shared.b16 {%0,%1,%2,%3}, [%4];"
                 : "=r"(r[0]), "=r"(r[1]), "=r"(r[2]), "=r"(r[3]) : "r"(addr));
}
__device__ __forceinline__ void mma16816(float* d, const u32* a, const u32* b) {
    asm volatile(
        "mma.sync.aligned.m16n8k16.row.col.f32.bf16.bf16.f32 "
        "{%0,%1,%2,%3}, {%4,%5,%6,%7}, {%8,%9}, {%0,%1,%2,%3};"
        : "+f"(d[0]), "+f"(d[1]), "+f"(d[2]), "+f"(d[3])
        : "r"(a[0]), "r"(a[1]), "r"(a[2]), "r"(a[3]), "r"(b[0]), "r"(b[1]));
}

// W tile swizzle: [rows][64B], 16B slots (same as proven R9 layout)
__device__ __forceinline__ u32 aoff(int row, int slot) {
    const int key = (row & 3) ^ ((row >> 2) & 1);
    return (u32)(row * 64 + ((slot ^ key) << 4));
}
// scores tile swizzle
__device__ __forceinline__ u32 soff(int r, int slot) {
    return (u32)(r * 64 + ((slot ^ ((r >> 1) & 3)) << 4));
}

// =====================================================================
// K0: pre-split weights (Wx, Wt transposed [u][k]; Wa transposed [h][u])
// =====================================================================
__global__ void k_prep(const float* __restrict__ kx, const float* __restrict__ kt,
                       const float* __restrict__ ka) {
    const int i = blockIdx.x * 256 + threadIdx.x;   // 0..16383
    {   // kx/kt: i = k*32 + u
        const int k = i >> 5, u = i & 31;
        float w = kx[i];
        __nv_bfloat16 h = __float2bfloat16_rn(w);
        g_wb[0][u * HH + k] = h;
        g_wb[1][u * HH + k] = __float2bfloat16_rn(w - __bfloat162float(h));
        w = kt[i];
        h = __float2bfloat16_rn(w);
        g_wb[2][u * HH + k] = h;
        g_wb[3][u * HH + k] = __float2bfloat16_rn(w - __bfloat162float(h));
    }
    {   // ka: i = u*512 + h  ->  g_wa[.][h*32 + u]
        const int u = i >> 9, h = i & 511;
        const float w = ka[i];
        const __nv_bfloat16 hb = __float2bfloat16_rn(w);
        g_wa[0][h * UU + u] = hb;
        g_wa[1][h * UU + u] = __float2bfloat16_rn(w - __bfloat162float(hb));
    }
}

// =====================================================================
// K1 (HMMA, A-direct): delta = lambd*tanh(x@Wx+bx)+(1-lambd)*tanh(t@Wt+bt)
// 256 threads, 8 warps; warp = 32 rows x 32 u; CTA = 256 rows.
// A (x,t) loaded f32 straight into fragment regs (LDG.64, full sectors),
// split to bf16 hi/lo in-register. Only W lives in smem (64KB k-half).
// No barriers inside the k-loop. 3-term split: ah@bh + ah@bl + al@bh.
// =====================================================================
#define DW_SMEM 65536   // 4 tensors x 8 chunks x 2KB

__global__ void __launch_bounds__(256, 2)
k_delta(const float* __restrict__ x, const float* __restrict__ t,
        const float* __restrict__ bx, const float* __restrict__ bt,
        const float* __restrict__ lambd)
{
    __shared__ __align__(16) char sW[DW_SMEM];
    const u32 sWa = (u32)__cvta_generic_to_shared(sW);

    const int tid = threadIdx.x;
    const int wid = tid >> 5;
    const int lane = tid & 31;
    const int rowBase = blockIdx.x * 256;
    const int row0 = rowBase + wid * 32;

    if (blockIdx.x < 64) g_sum[blockIdx.x * 256 + tid] = 0.0f;

    float accG[2][4][4], accB[2][4][4];
#pragma unroll
    for (int rg = 0; rg < 2; rg++)
#pragma unroll
        for (int j = 0; j < 4; j++)
#pragma unroll
            for (int q = 0; q < 4; q++) { accG[rg][j][q] = 0.0f; accB[rg][j][q] = 0.0f; }

    // A fragment base: row = row0 + (lane>>2) [+8 / +16 rg], k = (lane&3)*2 [+8]
    const char* xb = (const char*)(x + (size_t)(row0 + (lane >> 2)) * HH + (lane & 3) * 2);
    const char* tb = (const char*)(t + (size_t)(row0 + (lane >> 2)) * HH + (lane & 3) * 2);

    // B fragment smem params (proven R9 mapping)
    const int bu = ((lane >> 4) & 1) * 8 + (lane & 7);
    const int bc0 = (lane >> 3) & 1;

    for (int half = 0; half < 2; half++) {
        __syncthreads();
        // stage W k-half: 4 tensors x 8 chunks x [32u][64B] swizzled
#pragma unroll
        for (int p = 0; p < 16; p++) {
            const int j = tid + 256 * p;
            const int sl = j & 3, u = (j >> 2) & 31, c = (j >> 7) & 7, ts = j >> 10;
            *(uint4*)(sW + ts * 16384 + c * 2048 + aoff(u, sl)) =
                *(const uint4*)((const char*)g_wb[ts] + u * 1024 + half * 512 + c * 64 + sl * 16);
        }
        __syncthreads();

        for (int c = 0; c < 8; c++) {
#pragma unroll
            for (int s = 0; s < 2; s++) {
                const u32 kbyte = (u32)((half * 256 + c * 32 + s * 16) * 4);
                const u32 wb0 = aoff(bu, bc0 + 2 * s);
                const u32 wb1 = aoff(bu + 16, bc0 + 2 * s);
                const u32 wtile = sWa + c * 2048;

                // ---- gamma: x vs Wx ----
                u32 bh[8], bl[8];
                ldm4(bh + 0, wtile + 0 * 16384 + wb0);
                ldm4(bh + 4, wtile + 0 * 16384 + wb1);
                ldm4(bl + 0, wtile + 1 * 16384 + wb0);
                ldm4(bl + 4, wtile + 1 * 16384 + wb1);
#pragma unroll
                for (int rg = 0; rg < 2; rg++) {
                    const char* p0 = xb + rg * 32768 + kbyte;
                    float2 f0 = *(const float2*)(p0);
                    float2 f1 = *(const float2*)(p0 + 16384);
                    float2 f2 = *(const float2*)(p0 + 32);
                    float2 f3 = *(const float2*)(p0 + 16384 + 32);
                    u32 ah[4], al[4];
                    cvt2(f0, ah[0], al[0]);
                    cvt2(f1, ah[1], al[1]);
                    cvt2(f2, ah[2], al[2]);
                    cvt2(f3, ah[3], al[3]);
#pragma unroll
                    for (int j = 0; j < 4; j++) {
                        mma16816(accG[rg][j], ah, bh + 2 * j);
                        mma16816(accG[rg][j], ah, bl + 2 * j);
                        mma16816(accG[rg][j], al, bh + 2 * j);
                    }
                }

                // ---- beta: t vs Wt ----
                ldm4(bh + 0, wtile + 2 * 16384 + wb0);
                ldm4(bh + 4, wtile + 2 * 16384 + wb1);
                ldm4(bl + 0, wtile + 3 * 16384 + wb0);
                ldm4(bl + 4, wtile + 3 * 16384 + wb1);
#pragma unroll
                for (int rg = 0; rg < 2; rg++) {
                    const char* p0 = tb + rg * 32768 + kbyte;
                    float2 f0 = *(const float2*)(p0);
                    float2 f1 = *(const float2*)(p0 + 16384);
                    float2 f2 = *(const float2*)(p0 + 32);
                    float2 f3 = *(const float2*)(p0 + 16384 + 32);
                    u32 ah[4], al[4];
                    cvt2(f0, ah[0], al[0]);
                    cvt2(f1, ah[1], al[1]);
                    cvt2(f2, ah[2], al[2]);
                    cvt2(f3, ah[3], al[3]);
#pragma unroll
                    for (int j = 0; j < 4; j++) {
                        mma16816(accB[rg][j], ah, bh + 2 * j);
                        mma16816(accB[rg][j], ah, bl + 2 * j);
                        mma16816(accB[rg][j], al, bh + 2 * j);
                    }
                }
            }
        }
    }

    // ---- epilogue: bias + tanh + lambda combine -> g_dhi/g_dlo ----
#pragma unroll
    for (int rg = 0; rg < 2; rg++) {
        const int rowL = row0 + rg * 16 + (lane >> 2);
        const int rowH = rowL + 8;
        const float lamL = __ldg(lambd + (rowL & (TT - 1)));
        const float lamH = __ldg(lambd + (rowH & (TT - 1)));
#pragma unroll
        for (int j = 0; j < 4; j++) {
            const int u0 = j * 8 + (lane & 3) * 2;
            const float bx0 = __ldg(bx + u0), bx1 = __ldg(bx + u0 + 1);
            const float bt0 = __ldg(bt + u0), bt1 = __ldg(bt + u0 + 1);
            float2 oL, oH;
            oL.x = lamL * fast_tanh(accG[rg][j][0] + bx0) + (1.0f - lamL) * fast_tanh(accB[rg][j][0] + bt0);
            oL.y = lamL * fast_tanh(accG[rg][j][1] + bx1) + (1.0f - lamL) * fast_tanh(accB[rg][j][1] + bt1);
            oH.x = lamH * fast_tanh(accG[rg][j][2] + bx0) + (1.0f - lamH) * fast_tanh(accB[rg][j][2] + bt0);
            oH.y = lamH * fast_tanh(accG[rg][j][3] + bx1) + (1.0f - lamH) * fast_tanh(accB[rg][j][3] + bt1);

            __nv_bfloat162 h2 = __float22bfloat162_rn(oL);
            float2 hf = __bfloat1622float2(h2);
            *(__nv_bfloat162*)(g_dhi + (size_t)rowL * UU + u0) = h2;
            *(__nv_bfloat162*)(g_dlo + (size_t)rowL * UU + u0) =
                __float22bfloat162_rn(make_float2(oL.x - hf.x, oL.y - hf.y));
            h2 = __float22bfloat162_rn(oH);
            hf = __bfloat1622float2(h2);
            *(__nv_bfloat162*)(g_dhi + (size_t)rowH * UU + u0) = h2;
            *(__nv_bfloat162*)(g_dlo + (size_t)rowH * UU + u0) =
                __float22bfloat162_rn(make_float2(oH.x - hf.x, oH.y - hf.y));
        }
    }
}

// =====================================================================
// shared GEMM core for scores (unchanged from R11)
// =====================================================================
#define K2S_BH 0
#define K2S_BL 32768
#define K2S_AH 65536
#define K2S_AL 69632
#define K2S_SUM 73728
#define K2_SMEM (K2S_SUM + HH*4)   // 75776

__device__ __forceinline__ void scores_gemm(char* smem, u32 sb, int rowBase,
                                            int tid, float acc[16][4]) {
#pragma unroll
    for (int p = 0; p < 4; p++) {
        const int i = tid + 512 * p;          // 0..2047
        const int h = i >> 2, sl = i & 3;
        const u32 d = soff(h, sl);
        *(uint4*)(smem + K2S_BH + d) = *(const uint4*)((const char*)g_wa[0] + h * 64 + sl * 16);
        *(uint4*)(smem + K2S_BL + d) = *(const uint4*)((const char*)g_wa[1] + h * 64 + sl * 16);
    }
    {
        const int i = tid & 255;
        const int r = i >> 2, sl = i & 3;
        const u32 d = soff(r, sl);
        const size_t go = (size_t)(rowBase + r) * 64 + sl * 16;
        if (tid < 256)
            *(uint4*)(smem + K2S_AH + d) = *(const uint4*)((const char*)g_dhi + go);
        else
            *(uint4*)(smem + K2S_AL + d) = *(const uint4*)((const char*)g_dlo + go);
    }
    __syncthreads();

    const int lane = tid & 31;
    const int wid = tid >> 5;
    const int g = lane >> 3, l = lane & 7;
    const int rt = wid & 3;
    const int hq = wid >> 2;

#pragma unroll
    for (int s = 0; s < 2; s++) {
        u32 ah[4], al[4];
        const u32 ao = soff(rt * 16 + (g & 1) * 8 + l, 2 * s + (g >> 1));
        ldm4(ah, sb + K2S_AH + ao);
        ldm4(al, sb + K2S_AL + ao);
#pragma unroll
        for (int nt = 0; nt < 8; nt++) {
            const int h0 = hq * 128 + nt * 16;
            const u32 bo = soff(h0 + (g >> 1) * 8 + l, 2 * s + (g & 1));
            u32 bh[4], bl[4];
            ldm4(bh, sb + K2S_BH + bo);
            ldm4(bl, sb + K2S_BL + bo);
            mma16816(acc[2 * nt],     ah, bh);
            mma16816(acc[2 * nt],     ah, bl);
            mma16816(acc[2 * nt],     al, bh);
            mma16816(acc[2 * nt + 1], ah, bh + 2);
            mma16816(acc[2 * nt + 1], ah, bl + 2);
            mma16816(acc[2 * nt + 1], al, bh + 2);
        }
    }
}

// =====================================================================
// K2a: sums only — g_sum[b,h] += sum_rows exp(score).
// =====================================================================
__global__ void __launch_bounds__(512, 1)
k_ssum(int dummy) {
    extern __shared__ char smem[];
    const u32 sb = (u32)__cvta_generic_to_shared(smem);
    float* ssum = (float*)(smem + K2S_SUM);

    const int tid = threadIdx.x;
    const int lane = tid & 31;
    const int wid = tid >> 5;
    const int rowBase = blockIdx.x * 64;

    ssum[tid] = 0.0f;

    float acc[16][4];
#pragma unroll
    for (int n = 0; n < 16; n++)
#pragma unroll
        for (int q = 0; q < 4; q++) acc[n][q] = 0.0f;

    scores_gemm(smem, sb, rowBase, tid, acc);

    const int hq = wid >> 2;
#pragma unroll
    for (int n8 = 0; n8 < 16; n8++) {
        const int h = hq * 128 + n8 * 8 + (lane & 3) * 2;
        float s0 = __expf(acc[n8][0]) + __expf(acc[n8][2]);
        float s1 = __expf(acc[n8][1]) + __expf(acc[n8][3]);
        s0 += __shfl_xor_sync(0xffffffffu, s0, 4);
        s0 += __shfl_xor_sync(0xffffffffu, s0, 8);
        s0 += __shfl_xor_sync(0xffffffffu, s0, 16);
        s1 += __shfl_xor_sync(0xffffffffu, s1, 4);
        s1 += __shfl_xor_sync(0xffffffffu, s1, 8);
        s1 += __shfl_xor_sync(0xffffffffu, s1, 16);
        if (lane < 4) {
            atomicAdd(&ssum[h], s0);
            atomicAdd(&ssum[h + 1], s1);
        }
    }
    __syncthreads();

    const int b = blockIdx.x >> 5;
    atomicAdd(&g_sum[b * HH + tid], ssum[tid]);
}

// =====================================================================
// K2b: recompute scores, alpha = exp(score)/sum -> out (single write).
// =====================================================================
__global__ void __launch_bounds__(512, 1)
k_norm(float* __restrict__ out) {
    extern __shared__ char smem[];
    const u32 sb = (u32)__cvta_generic_to_shared(smem);
    float* sinv = (float*)(smem + K2S_SUM);

    const int tid = threadIdx.x;
    const int lane = tid & 31;
    const int wid = tid >> 5;
    const int rowBase = blockIdx.x * 64;
    const int b = blockIdx.x >> 5;

    sinv[tid] = 1.0f / g_sum[b * HH + tid];

    float acc[16][4];
#pragma unroll
    for (int n = 0; n < 16; n++)
#pragma unroll
        for (int q = 0; q < 4; q++) acc[n][q] = 0.0f;

    scores_gemm(smem, sb, rowBase, tid, acc);

    const int rt = wid & 3;
    const int hq = wid >> 2;
    const int rowL = rowBase + rt * 16 + (lane >> 2);
    float* oL = out + (size_t)rowL * HH;
    float* oH = oL + 8 * HH;
#pragma unroll
    for (int n8 = 0; n8 < 16; n8++) {
        const int h = hq * 128 + n8 * 8 + (lane & 3) * 2;
        const float2 inv = *(const float2*)(sinv + h);
        *(float2*)(oL + h) = make_float2(__expf(acc[n8][0]) * inv.x,
                                         __expf(acc[n8][1]) * inv.y);
        *(float2*)(oH + h) = make_float2(__expf(acc[n8][2]) * inv.x,
                                         __expf(acc[n8][3]) * inv.y);
    }
}

// =====================================================================
extern "C" void kernel_launch(void* const* d_in, const int* in_sizes, int n_in,
                              void* d_out, int out_size) {
    const float* x     = (const float*)d_in[0];
    const float* t     = (const float*)d_in[1];
    const float* kx    = (const float*)d_in[2];
    const float* kt    = (const float*)d_in[3];
    const float* ka    = (const float*)d_in[4];
    const float* bx    = (const float*)d_in[5];
    const float* bt    = (const float*)d_in[6];
    const float* lambd = (const float*)d_in[7];
    float* out = (float*)d_out;

    cudaFuncSetAttribute(k_ssum, cudaFuncAttributeMaxDynamicSharedMemorySize, K2_SMEM);
    cudaFuncSetAttribute(k_norm, cudaFuncAttributeMaxDynamicSharedMemorySize, K2_SMEM);

    k_prep<<<HH * UU / 256, 256>>>(kx, kt, ka);
    k_delta<<<ROWS / 256, 256>>>(x, t, bx, bt, lambd);
    k_ssum<<<ROWS / 64, 512, K2_SMEM>>>(0);
    k_norm<<<ROWS / 64, 512, K2_SMEM>>>(out);
}